// round 12
// baseline (speedup 1.0000x reference)
#include <cuda_runtime.h>
#include <math.h>

#define NBLK 128
#define NTHR 1024
#define H    256
#define HE   64
#define APER 64
#define NPER 512
#define EPSF 1e-8f
#define INFM 1000000.0f
#define MU_STEP (20.0f/63.0f)
#define INV_SIG (64.0f/20.0f)

typedef unsigned long long u64;

// ------------------------- scratch (device globals) --------------------------
__device__ float g_wc  [16*256*320];   // split-K16 partials
__device__ float g_aux [640];          // [0:256) wqbk, [256:576) biasc, [576] bq.bk
__device__ float g_qke [8*512*320];    // split-K8
__device__ float g_attn[512*512];      // softmax probs
__device__ float g_nt  [8*512*256];    // n_tilde partials (split-K8)
__device__ float g_cb  [512*320];      // s lives in columns [256,320)
__device__ float g_upd [10*512*256];   // split-K10
__device__ float g_af  [512*256];
__device__ float g_m1  [8*512*512];    // split-K8
__device__ float g_m2  [8*512*512];    // split-K8
__device__ float g_m3  [16*512*256];   // split-K16

__device__ unsigned g_bar_count = 0;
__device__ unsigned g_bar_epoch = 0;

// ------------------------- f32x2 helpers ---------------------------------------
__device__ __forceinline__ void ffma2(u64 &d, u64 a, u64 b){
  asm("fma.rn.f32x2 %0, %1, %2, %0;" : "+l"(d) : "l"(a), "l"(b));
}
__device__ __forceinline__ u64 pack2(float x, float y){
  u64 r; asm("mov.b64 %0, {%1, %2};" : "=l"(r) : "f"(x), "f"(y)); return r;
}
__device__ __forceinline__ float2 unpack2(u64 v){
  float2 r; asm("mov.b64 {%0, %1}, %2;" : "=f"(r.x), "=f"(r.y) : "l"(v)); return r;
}

// ------------------------- reductions -----------------------------------------
__device__ __forceinline__ float warp_reduce_sum(float v){
#pragma unroll
  for (int o=16;o>0;o>>=1) v += __shfl_xor_sync(0xffffffffu, v, o);
  return v;
}
__device__ __forceinline__ float warp_reduce_max(float v){
#pragma unroll
  for (int o=16;o>0;o>>=1) v = fmaxf(v, __shfl_xor_sync(0xffffffffu, v, o));
  return v;
}

// Software grid barrier (128 blocks, 1 per SM -> co-resident, deadlock-free).
__device__ __forceinline__ void grid_barrier(){
  __syncthreads();
  if (threadIdx.x == 0){
    __threadfence();
    unsigned e = atomicAdd(&g_bar_epoch, 0u);
    unsigned prev = atomicAdd(&g_bar_count, 1u);
    if (prev == gridDim.x - 1){
      atomicExch(&g_bar_count, 0u);
      __threadfence();
      atomicAdd(&g_bar_epoch, 1u);
    } else {
      volatile unsigned* ep = (volatile unsigned*)&g_bar_epoch;
      while (*ep == e) { }
      __threadfence();
    }
  }
  __syncthreads();
}

// Named barrier: syncs one 256-thread quarter independently.
__device__ __forceinline__ void q_sync(int q){
  asm volatile("bar.sync %0, 256;" :: "r"(1 + q) : "memory");
}

// ------------------------- shared memory ---------------------------------------
struct GemmSmem { float As[2][16][68]; float Bs[2][16][68]; };   // 17.0 KB
struct AttnA    { float qk[4][H]; float qek[4][HE]; float logit[4][NPER]; };
struct Smem {
  union U { GemmSmem g[4]; AttnA a; } u;      // 68 KB
  float dist[4][NPER];                        // 8 KB
  float ax[4][3];
  float qbk[4];
  int   list[NPER];
  int   cnt;
  float red[32];
};

// ------------------------- GEMM tile 64x64, 256 thr/instance, FFMA2 ------------
// A_KM : A is K-major (A[k*lda+m]); else row-major.
// APART: >0 -> A := relu(sum_{p<APART} A[p*astride] + abias[k]) on load.
// B_KN : B is (K,N) row-major; else (N,K) row-major. BPART: >1 -> sum partials.
// UPD  : A-load = sum8 g_nt (k<256) | g_cb s (k>=256).
template<bool A_KM, int APART, bool B_KN, int BPART, bool UPD>
__device__ void gemm_tile(const float* __restrict__ A, int lda, size_t astride,
                          const float* __restrict__ abias,
                          const float* __restrict__ B, int ldb, size_t bstride,
                          float* __restrict__ C, int ldc,
                          int m0, int n0, int kbeg, int kend,
                          GemmSmem* sm, int q)
{
  const int t  = threadIdx.x & 255;
  const int tx = t & 15, ty = t >> 4;

  int a_i0, a_i1, b_i0, b_i1;
  if (A_KM){ a_i0 = t >> 4; a_i1 = t & 15; }     // k-row(16), m-grp(16)
  else     { a_i0 = t >> 2; a_i1 = t & 3;  }     // m-row(64), k-grp(4)
  if (B_KN){ b_i0 = t >> 4; b_i1 = t & 15; }     // k-row(16), n-grp(16)
  else     { b_i0 = t >> 2; b_i1 = t & 3;  }     // n-row(64), k-grp(4)

  auto loadA = [&](int k0)->float4 {
    if (UPD){
      const int col = k0 + a_i1*4;
      const int row = m0 + a_i0;
      if (col < 256){
        const size_t o = (size_t)row*256 + col;
        float4 v = *(const float4*)(g_nt + o);
#pragma unroll
        for (int p = 1; p < 8; p++){
          float4 w = *(const float4*)(g_nt + (size_t)p*131072 + o);
          v.x+=w.x; v.y+=w.y; v.z+=w.z; v.w+=w.w;
        }
        return v;
      }
      return *(const float4*)(g_cb + (size_t)row*320 + col);
    }
    if (A_KM)
      return *(const float4*)(A + (size_t)(k0 + a_i0)*lda + m0 + a_i1*4);
    const size_t o = (size_t)(m0 + a_i0)*lda + k0 + a_i1*4;
    if (APART == 0) return *(const float4*)(A + o);
    float4 v = *(const float4*)(A + o);
#pragma unroll
    for (int p = 1; p < APART; p++){
      float4 w = *(const float4*)(A + p*astride + o);
      v.x+=w.x; v.y+=w.y; v.z+=w.z; v.w+=w.w;
    }
    float4 vb = *(const float4*)(abias + k0 + a_i1*4);
    v.x = fmaxf(v.x+vb.x, 0.f); v.y = fmaxf(v.y+vb.y, 0.f);
    v.z = fmaxf(v.z+vb.z, 0.f); v.w = fmaxf(v.w+vb.w, 0.f);
    return v;
  };
  auto loadB = [&](int k0)->float4 {
    if (B_KN){
      const size_t o = (size_t)(k0 + b_i0)*ldb + n0 + b_i1*4;
      float4 v = *(const float4*)(B + o);
#pragma unroll
      for (int p = 1; p < BPART; p++){
        float4 w = *(const float4*)(B + p*bstride + o);
        v.x+=w.x; v.y+=w.y; v.z+=w.z; v.w+=w.w;
      }
      return v;
    }
    return *(const float4*)(B + (size_t)(n0 + b_i0)*ldb + k0 + b_i1*4);
  };
  auto storeA = [&](int buf, float4 v){
    if (A_KM) *(float4*)&sm->As[buf][a_i0][a_i1*4] = v;
    else {
      sm->As[buf][a_i1*4+0][a_i0] = v.x;
      sm->As[buf][a_i1*4+1][a_i0] = v.y;
      sm->As[buf][a_i1*4+2][a_i0] = v.z;
      sm->As[buf][a_i1*4+3][a_i0] = v.w;
    }
  };
  auto storeB = [&](int buf, float4 v){
    if (B_KN) *(float4*)&sm->Bs[buf][b_i0][b_i1*4] = v;
    else {
      sm->Bs[buf][b_i1*4+0][b_i0] = v.x;
      sm->Bs[buf][b_i1*4+1][b_i0] = v.y;
      sm->Bs[buf][b_i1*4+2][b_i0] = v.z;
      sm->Bs[buf][b_i1*4+3][b_i0] = v.w;
    }
  };

  u64 acc[2][4];
#pragma unroll
  for (int i=0;i<2;i++)
#pragma unroll
    for (int j=0;j<4;j++) acc[i][j] = 0ULL;

  q_sync(q);                           // protect smem union reuse
  storeA(0, loadA(kbeg));
  storeB(0, loadB(kbeg));
  q_sync(q);

  int buf = 0;
  for (int k0 = kbeg + 16; ; k0 += 16, buf ^= 1){
    const bool more = (k0 < kend);
    float4 pa, pb;
    if (more){ pa = loadA(k0); pb = loadB(k0); }
#pragma unroll
    for (int kk = 0; kk < 16; kk++){
      ulonglong2 aa = *(const ulonglong2*)&sm->As[buf][kk][ty*4];
      float4 bv = *(const float4*)&sm->Bs[buf][kk][tx*4];
      u64 b0 = pack2(bv.x, bv.x), b1 = pack2(bv.y, bv.y);
      u64 b2 = pack2(bv.z, bv.z), b3 = pack2(bv.w, bv.w);
      ffma2(acc[0][0], aa.x, b0); ffma2(acc[0][1], aa.x, b1);
      ffma2(acc[0][2], aa.x, b2); ffma2(acc[0][3], aa.x, b3);
      ffma2(acc[1][0], aa.y, b0); ffma2(acc[1][1], aa.y, b1);
      ffma2(acc[1][2], aa.y, b2); ffma2(acc[1][3], aa.y, b3);
    }
    if (!more) break;
    storeA(buf^1, pa);
    storeB(buf^1, pb);
    q_sync(q);
  }

  float2 r0[4], r1[4];
#pragma unroll
  for (int j=0;j<4;j++){ r0[j] = unpack2(acc[0][j]); r1[j] = unpack2(acc[1][j]); }
  const int m = m0 + ty*4;
  *(float4*)(C + (size_t)(m+0)*ldc + n0 + tx*4) = make_float4(r0[0].x, r0[1].x, r0[2].x, r0[3].x);
  *(float4*)(C + (size_t)(m+1)*ldc + n0 + tx*4) = make_float4(r0[0].y, r0[1].y, r0[2].y, r0[3].y);
  *(float4*)(C + (size_t)(m+2)*ldc + n0 + tx*4) = make_float4(r1[0].x, r1[1].x, r1[2].x, r1[3].x);
  *(float4*)(C + (size_t)(m+3)*ldc + n0 + tx*4) = make_float4(r1[0].y, r1[1].y, r1[2].y, r1[3].y);
}

// ------------------------- residual + LN (4 rows/block, P partials) ------------
template<int P>
__device__ void lnP(const float* __restrict__ r,
                    const float* __restrict__ part, size_t pstride,
                    const float* __restrict__ bias,
                    const float* __restrict__ g, const float* __restrict__ b,
                    float* __restrict__ o)
{
  const int w = threadIdx.x >> 5, lane = threadIdx.x & 31;
  if (w >= 4) return;
  const size_t row = (size_t)blockIdx.x*4 + w;
  float v[8]; float s = 0.f;
#pragma unroll
  for (int i=0;i<8;i++){
    int c = lane + i*32;
    size_t idx = row*H + c;
    float x = r[idx] + bias[c];
#pragma unroll
    for (int p=0;p<P;p++) x += part[(size_t)p*pstride + idx];
    v[i] = x; s += x;
  }
  s = warp_reduce_sum(s);
  float mean = s * (1.f/H);
  float s2 = 0.f;
#pragma unroll
  for (int i=0;i<8;i++){ float d = v[i]-mean; s2 += d*d; }
  s2 = warp_reduce_sum(s2);
  float inv = rsqrtf(s2*(1.f/H) + 1e-5f);
#pragma unroll
  for (int i=0;i<8;i++){
    int c = lane + i*32;
    o[row*H+c] = (v[i]-mean)*inv*g[c] + b[c];
  }
}

// ------------------------- megakernel ------------------------------------------
__global__ __launch_bounds__(NTHR)
void mega(const float* __restrict__ anchor_x,
          const float* __restrict__ node_x,
          const float* __restrict__ afeat,
          const float* __restrict__ nf,
          const float* __restrict__ nmask,
          const float* __restrict__ Wq,  const float* __restrict__ bq,
          const float* __restrict__ Wkv, const float* __restrict__ bkv,
          const float* __restrict__ ln1g, const float* __restrict__ ln1b,
          const float* __restrict__ W1, const float* __restrict__ b1,
          const float* __restrict__ W2, const float* __restrict__ b2,
          const float* __restrict__ W3, const float* __restrict__ b3,
          const float* __restrict__ ln2g, const float* __restrict__ ln2b,
          float* __restrict__ out)
{
  extern __shared__ char s_raw[];
  Smem* S = reinterpret_cast<Smem*>(s_raw);

  const int tid = threadIdx.x, bid = blockIdx.x;
  const int lane = tid & 31, warp = tid >> 5;
  const int q = tid >> 8;                          // quarter 0..3
  GemmSmem* gs = &S->u.g[q];
  const int inst = bid*4 + q;                      // 0..511 tile instances
  const int a0 = bid*4;
  const int nbase = (a0 / APER) * NPER;

  // ========== stage A: wc (20 tiles x splitK16 = 320 inst) + aux ===============
  if (bid < 80){
    int z = inst / 20, tt = inst % 20, my = tt / 5, nx = tt % 5;
    gemm_tile<true,0,true,1,false>(Wq,256,0, nullptr, Wkv,320,0,
        g_wc + (size_t)z*81920, 320, my*64, nx*64, z*16, z*16+16, gs, q);
  } else if (bid == 100){
    for (int i = tid; i < 256; i += NTHR){
      float s = 0.f;
      for (int j = 0; j < 256; j++) s = fmaf(Wq[(size_t)j*256 + i], bkv[j], s);
      g_aux[i] = s;
    }
  } else if (bid == 101){
    for (int c = tid; c < 320; c += NTHR){
      float s = 0.f;
      for (int j = 0; j < 256; j++) s = fmaf(bq[j], Wkv[(size_t)j*320 + c], s);
      g_aux[256 + c] = s;
    }
  } else if (bid == 102 && tid == 0){
    float s = 0.f;
    for (int j = 0; j < 256; j++) s = fmaf(bq[j], bkv[j], s);
    g_aux[576] = s;
  }
  grid_barrier();

  // ========== stage B: attn prep + qke (40 tiles x splitK8 = 320 inst) =========
  if (tid == 0) S->cnt = 0;
  if (tid < 12) S->ax[tid/3][tid%3] = anchor_x[(size_t)(a0 + tid/3)*3 + (tid%3)];
  __syncthreads();
  if (tid < NPER){
    const int n = tid, ng = nbase + n;
    const float x0 = node_x[(size_t)3*ng+0];
    const float x1 = node_x[(size_t)3*ng+1];
    const float x2 = node_x[(size_t)3*ng+2];
#pragma unroll
    for (int a=0;a<4;a++){
      float dx = S->ax[a][0]-x0+EPSF;
      float dy = S->ax[a][1]-x1+EPSF;
      float dz = S->ax[a][2]-x2+EPSF;
      S->dist[a][n] = sqrtf(dx*dx + dy*dy + dz*dz);
    }
    if (nmask[ng] == 0.0f){
      int p = atomicAdd(&S->cnt, 1);
      S->list[p] = n;
    }
  }
  if (warp < 4){
    const float* ar = afeat + (size_t)(a0 + warp)*H;
    float s = 0.f;
#pragma unroll
    for (int kk=0;kk<8;kk++) s = fmaf(ar[lane+kk*32], g_aux[lane+kk*32], s);
    s = warp_reduce_sum(s);
    if (lane == 0) S->qbk[warp] = s + g_aux[576];
  }
  if (bid < 80){
    int z = inst / 40, tt = inst % 40, my = tt / 5, nx = tt % 5;
    gemm_tile<false,0,true,16,false>(afeat,256,0, nullptr,
        g_wc,320,81920,
        g_qke + (size_t)z*163840, 320, my*64, nx*64, z*32, z*32+32, gs, q);
  }
  grid_barrier();

  // ========== stage C: attention (logits, softmax, s-vector) ===================
  for (int i = tid; i < 4*NPER; i += NTHR)
    S->u.a.logit[i>>9][i & 511] = 0.f;
  for (int i = tid; i < 4*320; i += NTHR){
    int r = i / 320, c = i - r*320;
    size_t idx = (size_t)(a0 + r)*320 + c;
    float v = g_aux[256 + c];
#pragma unroll
    for (int p=0;p<8;p++) v += g_qke[(size_t)p*163840 + idx];
    if (c < 256) S->u.a.qk[r][c] = v; else S->u.a.qek[r][c-256] = v;
  }
  __syncthreads();

  {                                               // masked logits only (32 warps)
    const int cnt = S->cnt;
    const float mu0 = (float)lane * MU_STEP;
    const float mu1 = (float)(lane+32) * MU_STEP;
    for (int i = warp; i < cnt; i += 32){
      const int n = S->list[i], ng = nbase + n;
      const float4* nf4 = (const float4*)(nf + (size_t)ng*H);
      float4 u0 = nf4[lane], u1 = nf4[lane+32];
#pragma unroll
      for (int a=0;a<4;a++){
        float t2 = S->dist[a][n] * 0.1f;
        float z0 = (t2 - mu0)*INV_SIG, z1 = (t2 - mu1)*INV_SIG;
        float z0s = z0*z0, z1s = z1*z1;
        float acc = 0.f;
        if (z0s < 64.f) acc  = __expf(-z0s) * S->u.a.qek[a][lane];
        if (z1s < 64.f) acc += __expf(-z1s) * S->u.a.qek[a][lane+32];
        const float4* qa = (const float4*)S->u.a.qk[a];
        float4 q0 = qa[lane], q1 = qa[lane+32];
        acc = fmaf(u0.x,q0.x, fmaf(u0.y,q0.y, fmaf(u0.z,q0.z, fmaf(u0.w,q0.w, acc))));
        acc = fmaf(u1.x,q1.x, fmaf(u1.y,q1.y, fmaf(u1.z,q1.z, fmaf(u1.w,q1.w, acc))));
        acc = warp_reduce_sum(acc);
        if (lane == 0) S->u.a.logit[a][n] = (acc + S->qbk[a]) * (-INFM);
      }
    }
  }
  __syncthreads();

#pragma unroll
  for (int a=0;a<4;a++){                          // softmax over 512 per anchor
    float l = (tid < NPER) ? S->u.a.logit[a][tid] : -1e30f;
    float m = warp_reduce_max(l);
    if (lane == 0) S->red[warp] = m;
    __syncthreads();
    float mx = S->red[0];
#pragma unroll
    for (int k=1;k<32;k++) mx = fmaxf(mx, S->red[k]);
    __syncthreads();
    float e = (tid < NPER) ? __expf(l - mx) : 0.f;
    float s = warp_reduce_sum(e);
    if (lane == 0) S->red[warp] = s;
    __syncthreads();
    float sm = 0.f;
#pragma unroll
    for (int k=0;k<32;k++) sm += S->red[k];
    if (tid < NPER){
      float p = e / sm;
      S->u.a.logit[a][tid] = p;
      g_attn[(size_t)(a0+a)*NPER + tid] = p;
    }
    __syncthreads();
  }

  {                                               // C1: s[a][j] = sum attn*rbf
    const int a = tid >> 8, r = tid & 255, j = r >> 2, qq = r & 3;
    const float mu = (float)j * MU_STEP;
    float acc = 0.f;
    const int nb0 = qq * 128;
#pragma unroll 4
    for (int nn=0; nn<128; nn++){
      int n = nb0 + nn;
      float z = (S->dist[a][n]*0.1f - mu) * INV_SIG;
      float z2 = z*z;
      if (z2 < 60.f) acc = fmaf(S->u.a.logit[a][n], __expf(-z2), acc);
    }
    acc += __shfl_xor_sync(0xffffffffu, acc, 1);
    acc += __shfl_xor_sync(0xffffffffu, acc, 2);
    if (qq == 0) g_cb[(size_t)(a0+a)*320 + 256 + j] = acc;
  }
  grid_barrier();

  // ========== stage C2: n_tilde = attn @ nf (32 tiles x splitK8 = 256 inst) ====
  if (bid < 64){
    const int b = inst >> 5, rem = inst & 31, nx = rem >> 3, z = rem & 7;
    gemm_tile<false,0,true,1,false>(g_attn,512,0, nullptr,
        nf + (size_t)b*131072, 256, 0,
        g_nt + (size_t)z*131072, 256, b*64, nx*64, z*64, z*64+64, gs, q);
  }
  grid_barrier();

  // ========== stage D: upd (32 tiles x splitK10 = 320 inst, UPD A-load) ========
  if (bid < 80){
    const int z = inst / 32, tt = inst & 31, my = tt >> 2, nx = tt & 3;
    gemm_tile<false,0,false,1,true>(g_nt,256,0, nullptr,
        Wkv + (size_t)256*320,320,0,
        g_upd + (size_t)z*131072, 256, my*64, nx*64, z*32, z*32+32, gs, q);
  }
  grid_barrier();

  // ========== stage E: af = LN1(afeat + sum10(upd) + bkv_v) ====================
  lnP<10>(afeat, g_upd, 131072, bkv + 256, ln1g, ln1b, g_af);
  grid_barrier();

  // ========== stage F: m1 (64 tiles x splitK8 = 512 inst) ======================
  {
    const int z = inst >> 6, tt = inst & 63, my = tt >> 3, nx = tt & 7;
    gemm_tile<false,0,false,1,false>(g_af,256,0, nullptr, W1,256,0,
        g_m1 + (size_t)z*262144, 512, my*64, nx*64, z*32, z*32+32, gs, q);
  }
  grid_barrier();

  // ========== stage G: m2 (64 x splitK8); A = relu(sum8(m1)+b1) ================
  {
    const int z = inst >> 6, tt = inst & 63, my = tt >> 3, nx = tt & 7;
    gemm_tile<false,8,false,1,false>(g_m1,512,262144, b1, W2,512,0,
        g_m2 + (size_t)z*262144, 512, my*64, nx*64, z*64, z*64+64, gs, q);
  }
  grid_barrier();

  // ========== stage H: m3 (32 x splitK16); A = relu(sum8(m2)+b2) ===============
  {
    const int z = inst >> 5, tt = inst & 31, my = tt >> 2, nx = tt & 3;
    gemm_tile<false,8,false,1,false>(g_m2,512,262144, b2, W3,512,0,
        g_m3 + (size_t)z*131072, 256, my*64, nx*64, z*32, z*32+32, gs, q);
  }
  grid_barrier();

  // ========== stage I: out = LN2(af + sum16(m3) + b3) ==========================
  lnP<16>(g_af, g_m3, 131072, b3, ln2g, ln2b, out);
}

// ------------------------- launch ----------------------------------------------
extern "C" void kernel_launch(void* const* d_in, const int* in_sizes, int n_in,
                              void* d_out, int out_size)
{
  const float* anchor_x        = (const float*)d_in[0];
  const float* node_x          = (const float*)d_in[1];
  const float* anchor_features = (const float*)d_in[2];
  const float* node_features   = (const float*)d_in[3];
  const float* node_mask       = (const float*)d_in[6];
  const float* Wq              = (const float*)d_in[7];
  const float* bq              = (const float*)d_in[8];
  const float* Wkv             = (const float*)d_in[9];
  const float* bkv             = (const float*)d_in[10];
  const float* ln1_g           = (const float*)d_in[11];
  const float* ln1_b           = (const float*)d_in[12];
  const float* W1              = (const float*)d_in[13];
  const float* b1              = (const float*)d_in[14];
  const float* W2              = (const float*)d_in[15];
  const float* b2              = (const float*)d_in[16];
  const float* W3              = (const float*)d_in[17];
  const float* b3              = (const float*)d_in[18];
  const float* ln2_g           = (const float*)d_in[19];
  const float* ln2_b           = (const float*)d_in[20];
  float* out = (float*)d_out;

  const int smem = (int)sizeof(Smem);
  cudaFuncSetAttribute(mega, cudaFuncAttributeMaxDynamicSharedMemorySize, smem);

  mega<<<NBLK, NTHR, smem>>>(anchor_x, node_x, anchor_features, node_features,
                             node_mask, Wq, bq, Wkv, bkv, ln1_g, ln1_b,
                             W1, b1, W2, b2, W3, b3, ln2_g, ln2_b, out);
}

// round 13
// speedup vs baseline: 1.1874x; 1.1874x over previous
#include <cuda_runtime.h>
#include <math.h>

#define NBLK 128
#define NTHR 512
#define GSZ  16                 // blocks per group (one batch)
#define H    256
#define HE   64
#define APER 64
#define NPER 512
#define EPSF 1e-8f
#define INFM 1000000.0f
#define MU_STEP (20.0f/63.0f)
#define INV_SIG (64.0f/20.0f)

typedef unsigned long long u64;

// ------------------------- scratch (device globals) --------------------------
__device__ float g_q  [4*512*256];   // q partials (splitK4)
__device__ float g_qke[4*512*320];   // qke partials (splitK4)
__device__ float g_attn[512*512];    // softmax probs
__device__ float g_nt [8*512*256];   // n_tilde partials (splitK8)
__device__ float g_cb [512*320];     // s in cols [256,320)
__device__ float g_upd[5*512*256];   // upd partials (splitK5)
__device__ float g_af [512*256];
__device__ float g_m1 [4*512*512];
__device__ float g_m2 [4*512*512];
__device__ float g_m3 [8*512*256];

__device__ unsigned g_gcnt[8*32];    // per-group barrier (padded lines)
__device__ unsigned g_gep [8*32];

// ------------------------- f32x2 helpers ---------------------------------------
__device__ __forceinline__ void ffma2(u64 &d, u64 a, u64 b){
  asm("fma.rn.f32x2 %0, %1, %2, %0;" : "+l"(d) : "l"(a), "l"(b));
}
__device__ __forceinline__ u64 pack2(float x, float y){
  u64 r; asm("mov.b64 %0, {%1, %2};" : "=l"(r) : "f"(x), "f"(y)); return r;
}
__device__ __forceinline__ float2 unpack2(u64 v){
  float2 r; asm("mov.b64 {%0, %1}, %2;" : "=f"(r.x), "=f"(r.y) : "l"(v)); return r;
}

// ------------------------- reductions -----------------------------------------
__device__ __forceinline__ float warp_reduce_sum(float v){
#pragma unroll
  for (int o=16;o>0;o>>=1) v += __shfl_xor_sync(0xffffffffu, v, o);
  return v;
}
__device__ __forceinline__ float warp_reduce_max(float v){
#pragma unroll
  for (int o=16;o>0;o>>=1) v = fmaxf(v, __shfl_xor_sync(0xffffffffu, v, o));
  return v;
}

// Group barrier: 16 co-resident blocks of one group.
__device__ __forceinline__ void group_barrier(int gid){
  __syncthreads();
  if (threadIdx.x == 0){
    unsigned* cnt = &g_gcnt[gid*32];
    unsigned* ep  = &g_gep [gid*32];
    __threadfence();
    unsigned e = atomicAdd(ep, 0u);
    unsigned prev = atomicAdd(cnt, 1u);
    if (prev == GSZ - 1){
      atomicExch(cnt, 0u);
      __threadfence();
      atomicAdd(ep, 1u);
    } else {
      volatile unsigned* p = ep;
      while (*p == e) { }
      __threadfence();
    }
  }
  __syncthreads();
}

// Named barrier: syncs one 256-thread half independently.
__device__ __forceinline__ void half_sync(int half){
  asm volatile("bar.sync %0, 256;" :: "r"(1 + half) : "memory");
}

// ------------------------- shared memory ---------------------------------------
struct GemmSmem { float As[2][16][68]; float Bs[2][16][68]; };
struct AttnA    { float qk[4][H]; float qek[4][HE]; float logit[4][NPER]; };
union  __align__(16) SU { GemmSmem g[2]; AttnA a; };

// ------------------------- GEMM tile 64x64, 256 thr/instance, FFMA2 ------------
// A row-major. APART>0: A := (sum_{p<APART} A[p*astride]) + abias[k]; relu iff ARELU.
// UPD: A-load = sum8 g_nt (k<256) | g_cb s-cols (k>=256).
// B_KN: B is (K,N) row-major; else (N,K) row-major (@W.T form).
template<int APART, int ARELU, int UPD, bool B_KN>
__device__ void gemm_tile(const float* __restrict__ A, int lda, size_t astride,
                          const float* __restrict__ abias,
                          const float* __restrict__ B, int ldb,
                          float* __restrict__ C, int ldc,
                          int m0, int n0, int kbeg, int kend,
                          GemmSmem* sm, int half)
{
  const int t  = threadIdx.x & 255;
  const int tx = t & 15, ty = t >> 4;

  const int a_i0 = t >> 2, a_i1 = t & 3;         // m-row(64), k-grp(4)
  int b_i0, b_i1;
  if (B_KN){ b_i0 = t >> 4; b_i1 = t & 15; }     // k-row(16), n-grp(16)
  else     { b_i0 = t >> 2; b_i1 = t & 3;  }     // n-row(64), k-grp(4)

  auto loadA = [&](int k0)->float4 {
    if (UPD){
      const int col = k0 + a_i1*4;
      const int row = m0 + a_i0;
      if (col < 256){
        const size_t o = (size_t)row*256 + col;
        float4 v = *(const float4*)(g_nt + o);
#pragma unroll
        for (int p = 1; p < 8; p++){
          float4 w = *(const float4*)(g_nt + (size_t)p*131072 + o);
          v.x+=w.x; v.y+=w.y; v.z+=w.z; v.w+=w.w;
        }
        return v;
      }
      return *(const float4*)(g_cb + (size_t)row*320 + col);
    }
    const size_t o = (size_t)(m0 + a_i0)*lda + kbeg*0 + k0 + a_i1*4;
    float4 v = *(const float4*)(A + o);
    if (APART > 0){
#pragma unroll
      for (int p = 1; p < APART; p++){
        float4 w = *(const float4*)(A + p*astride + o);
        v.x+=w.x; v.y+=w.y; v.z+=w.z; v.w+=w.w;
      }
      float4 vb = *(const float4*)(abias + k0 + a_i1*4);
      v.x += vb.x; v.y += vb.y; v.z += vb.z; v.w += vb.w;
      if (ARELU){
        v.x = fmaxf(v.x,0.f); v.y = fmaxf(v.y,0.f);
        v.z = fmaxf(v.z,0.f); v.w = fmaxf(v.w,0.f);
      }
    }
    return v;
  };
  auto loadB = [&](int k0)->float4 {
    if (B_KN) return *(const float4*)(B + (size_t)(k0 + b_i0)*ldb + n0 + b_i1*4);
    return *(const float4*)(B + (size_t)(n0 + b_i0)*ldb + k0 + b_i1*4);
  };
  auto storeA = [&](int buf, float4 v){
    sm->As[buf][a_i1*4+0][a_i0] = v.x;
    sm->As[buf][a_i1*4+1][a_i0] = v.y;
    sm->As[buf][a_i1*4+2][a_i0] = v.z;
    sm->As[buf][a_i1*4+3][a_i0] = v.w;
  };
  auto storeB = [&](int buf, float4 v){
    if (B_KN) *(float4*)&sm->Bs[buf][b_i0][b_i1*4] = v;
    else {
      sm->Bs[buf][b_i1*4+0][b_i0] = v.x;
      sm->Bs[buf][b_i1*4+1][b_i0] = v.y;
      sm->Bs[buf][b_i1*4+2][b_i0] = v.z;
      sm->Bs[buf][b_i1*4+3][b_i0] = v.w;
    }
  };

  u64 acc[2][4];
#pragma unroll
  for (int i=0;i<2;i++)
#pragma unroll
    for (int j=0;j<4;j++) acc[i][j] = 0ULL;

  half_sync(half);
  storeA(0, loadA(kbeg));
  storeB(0, loadB(kbeg));
  half_sync(half);

  int buf = 0;
  for (int k0 = kbeg + 16; ; k0 += 16, buf ^= 1){
    const bool more = (k0 < kend);
    float4 pa, pb;
    if (more){ pa = loadA(k0); pb = loadB(k0); }
#pragma unroll
    for (int kk = 0; kk < 16; kk++){
      ulonglong2 aa = *(const ulonglong2*)&sm->As[buf][kk][ty*4];
      float4 bv = *(const float4*)&sm->Bs[buf][kk][tx*4];
      u64 b0 = pack2(bv.x, bv.x), b1 = pack2(bv.y, bv.y);
      u64 b2 = pack2(bv.z, bv.z), b3 = pack2(bv.w, bv.w);
      ffma2(acc[0][0], aa.x, b0); ffma2(acc[0][1], aa.x, b1);
      ffma2(acc[0][2], aa.x, b2); ffma2(acc[0][3], aa.x, b3);
      ffma2(acc[1][0], aa.y, b0); ffma2(acc[1][1], aa.y, b1);
      ffma2(acc[1][2], aa.y, b2); ffma2(acc[1][3], aa.y, b3);
    }
    if (!more) break;
    storeA(buf^1, pa);
    storeB(buf^1, pb);
    half_sync(half);
  }

  float2 r0[4], r1[4];
#pragma unroll
  for (int j=0;j<4;j++){ r0[j] = unpack2(acc[0][j]); r1[j] = unpack2(acc[1][j]); }
  const int m = m0 + ty*4;
  *(float4*)(C + (size_t)(m+0)*ldc + n0 + tx*4) = make_float4(r0[0].x, r0[1].x, r0[2].x, r0[3].x);
  *(float4*)(C + (size_t)(m+1)*ldc + n0 + tx*4) = make_float4(r0[0].y, r0[1].y, r0[2].y, r0[3].y);
  *(float4*)(C + (size_t)(m+2)*ldc + n0 + tx*4) = make_float4(r1[0].x, r1[1].x, r1[2].x, r1[3].x);
  *(float4*)(C + (size_t)(m+3)*ldc + n0 + tx*4) = make_float4(r1[0].y, r1[1].y, r1[2].y, r1[3].y);
}

// ------------------------- residual + LN (4 rows/block, P partials) ------------
template<int P>
__device__ void lnP(const float* __restrict__ r,
                    const float* __restrict__ part, size_t pstride,
                    const float* __restrict__ bias,
                    const float* __restrict__ g, const float* __restrict__ b,
                    float* __restrict__ o)
{
  const int w = threadIdx.x >> 5, lane = threadIdx.x & 31;
  if (w >= 4) return;
  const size_t row = (size_t)blockIdx.x*4 + w;
  float v[8]; float s = 0.f;
#pragma unroll
  for (int i=0;i<8;i++){
    int c = lane + i*32;
    size_t idx = row*H + c;
    float x = r[idx] + bias[c];
#pragma unroll
    for (int p=0;p<P;p++) x += part[(size_t)p*pstride + idx];
    v[i] = x; s += x;
  }
  s = warp_reduce_sum(s);
  float mean = s * (1.f/H);
  float s2 = 0.f;
#pragma unroll
  for (int i=0;i<8;i++){ float d = v[i]-mean; s2 += d*d; }
  s2 = warp_reduce_sum(s2);
  float inv = rsqrtf(s2*(1.f/H) + 1e-5f);
#pragma unroll
  for (int i=0;i<8;i++){
    int c = lane + i*32;
    o[row*H+c] = (v[i]-mean)*inv*g[c] + b[c];
  }
}

// ------------------------- megakernel ------------------------------------------
__global__ __launch_bounds__(NTHR)
void mega(const float* __restrict__ anchor_x,
          const float* __restrict__ node_x,
          const float* __restrict__ afeat,
          const float* __restrict__ nf,
          const float* __restrict__ nmask,
          const float* __restrict__ Wq,  const float* __restrict__ bq,
          const float* __restrict__ Wkv, const float* __restrict__ bkv,
          const float* __restrict__ ln1g, const float* __restrict__ ln1b,
          const float* __restrict__ W1, const float* __restrict__ b1,
          const float* __restrict__ W2, const float* __restrict__ b2,
          const float* __restrict__ W3, const float* __restrict__ b3,
          const float* __restrict__ ln2g, const float* __restrict__ ln2b,
          float* __restrict__ out)
{
  __shared__ SU su;
  __shared__ __align__(16) float s_dist[4][NPER];
  __shared__ float s_ax[4][3];
  __shared__ float s_qbk[4];
  __shared__ float s_bqbk;
  __shared__ int   s_list[NPER];
  __shared__ int   s_cnt;
  __shared__ float s_red[16];

  const int tid = threadIdx.x, bid = blockIdx.x;
  const int lane = tid & 31, warp = tid >> 5;
  const int half = tid >> 8;
  GemmSmem* gs = &su.g[half];
  const int gid  = bid >> 4;                      // group 0..7 (one batch)
  const int inst = half*GSZ + (bid & 15);         // 0..31 per group
  const int mrow = gid * 64;                      // group's anchor-row base
  const int a0   = bid * 4;                       // block's own anchors
  const int nbase = gid * NPER;

  // ========== S1: attn prep + bq.bk + q partials (4 tiles x splitK4 = 16) ======
  if (tid == 0) s_cnt = 0;
  if (tid < 12) s_ax[tid/3][tid%3] = anchor_x[(size_t)(a0 + tid/3)*3 + (tid%3)];
  __syncthreads();
  {
    const int n = tid & 511, ng = nbase + n;
    if (tid < NPER){
      const float x0 = node_x[(size_t)3*ng+0];
      const float x1 = node_x[(size_t)3*ng+1];
      const float x2 = node_x[(size_t)3*ng+2];
#pragma unroll
      for (int a=0;a<4;a++){
        float dx = s_ax[a][0]-x0+EPSF;
        float dy = s_ax[a][1]-x1+EPSF;
        float dz = s_ax[a][2]-x2+EPSF;
        s_dist[a][n] = sqrtf(dx*dx + dy*dy + dz*dz);
      }
      if (nmask[ng] == 0.0f){
        int p = atomicAdd(&s_cnt, 1);
        s_list[p] = n;
      }
    }
  }
  if (warp == 8){                                 // bq . bk
    float s = 0.f;
#pragma unroll
    for (int kk=0;kk<8;kk++) s = fmaf(bq[lane+kk*32], bkv[lane+kk*32], s);
    s = warp_reduce_sum(s);
    if (lane == 0) s_bqbk = s;
  }
  if (inst < 16){                                 // q = afeat @ Wq.T (partials)
    const int nx = inst & 3, z = inst >> 2;
    gemm_tile<0,0,0,false>(afeat,256,0, nullptr, Wq,256,
        g_q + (size_t)z*131072, 256, mrow, nx*64, z*64, z*64+64, gs, half);
  }
  group_barrier(gid);

  // ========== S2: qke = (sum q + bq) @ Wkv[0:256,:]  (5 tiles x splitK4 = 20) ==
  if (inst < 20){
    const int nx = inst % 5, z = inst / 5;
    gemm_tile<4,0,0,true>(g_q,256,131072, bq, Wkv,320,
        g_qke + (size_t)z*163840, 320, mrow, nx*64, z*64, z*64+64, gs, half);
  }
  group_barrier(gid);

  // ========== S3: attention (block-local) ======================================
  // qbk[a] = q[a].bkv + bq.bk
  if (warp < 4){
    const size_t row = (size_t)(a0 + warp)*256;
    float s = 0.f;
#pragma unroll
    for (int kk=0;kk<8;kk++){
      int c = lane + kk*32;
      float qv = g_q[row+c] + g_q[131072+row+c] + g_q[2*131072+row+c]
               + g_q[3*131072+row+c] + bq[c];
      s = fmaf(qv, bkv[c], s);
    }
    s = warp_reduce_sum(s);
    if (lane == 0) s_qbk[warp] = s + s_bqbk;
  }
  for (int i = tid; i < 4*NPER; i += NTHR)
    su.a.logit[i>>9][i & 511] = 0.f;
  for (int i = tid; i < 4*320; i += NTHR){
    int r = i / 320, c = i - r*320;
    size_t idx = (size_t)(a0 + r)*320 + c;
    float v = g_qke[idx] + g_qke[163840 + idx] + g_qke[2*163840 + idx]
            + g_qke[3*163840 + idx];
    if (c < 256) su.a.qk[r][c] = v; else su.a.qek[r][c-256] = v;
  }
  __syncthreads();

  {                                               // masked logits only
    const int cnt = s_cnt;
    const float mu0 = (float)lane * MU_STEP;
    const float mu1 = (float)(lane+32) * MU_STEP;
    for (int i = warp; i < cnt; i += 16){
      const int n = s_list[i], ng = nbase + n;
      const float4* nf4 = (const float4*)(nf + (size_t)ng*H);
      float4 u0 = nf4[lane], u1 = nf4[lane+32];
#pragma unroll
      for (int a=0;a<4;a++){
        float t2 = s_dist[a][n] * 0.1f;
        float z0 = (t2 - mu0)*INV_SIG, z1 = (t2 - mu1)*INV_SIG;
        float z0s = z0*z0, z1s = z1*z1;
        float acc = 0.f;
        if (z0s < 64.f) acc  = __expf(-z0s) * su.a.qek[a][lane];
        if (z1s < 64.f) acc += __expf(-z1s) * su.a.qek[a][lane+32];
        const float4* qa = (const float4*)su.a.qk[a];
        float4 q0 = qa[lane], q1 = qa[lane+32];
        acc = fmaf(u0.x,q0.x, fmaf(u0.y,q0.y, fmaf(u0.z,q0.z, fmaf(u0.w,q0.w, acc))));
        acc = fmaf(u1.x,q1.x, fmaf(u1.y,q1.y, fmaf(u1.z,q1.z, fmaf(u1.w,q1.w, acc))));
        acc = warp_reduce_sum(acc);
        if (lane == 0) su.a.logit[a][n] = (acc + s_qbk[a]) * (-INFM);
      }
    }
  }
  __syncthreads();

#pragma unroll
  for (int a=0;a<4;a++){                          // softmax over 512
    float l = su.a.logit[a][tid];
    float m = warp_reduce_max(l);
    if (lane == 0) s_red[warp] = m;
    __syncthreads();
    float mx = s_red[0];
#pragma unroll
    for (int k=1;k<16;k++) mx = fmaxf(mx, s_red[k]);
    float e = __expf(l - mx);
    float s = warp_reduce_sum(e);
    __syncthreads();
    if (lane == 0) s_red[warp] = s;
    __syncthreads();
    float sm = 0.f;
#pragma unroll
    for (int k=0;k<16;k++) sm += s_red[k];
    float p = e / sm;
    su.a.logit[a][tid] = p;
    g_attn[(size_t)(a0+a)*NPER + tid] = p;
    __syncthreads();
  }

  {                                               // C1: s[a][j] = sum attn*rbf
    const int a = tid >> 7, r = tid & 127, j = r >> 1, hh = r & 1;
    const float mu = (float)j * MU_STEP;
    float acc = 0.f;
    const int nb0 = hh * 256;
#pragma unroll 4
    for (int nn=0; nn<256; nn++){
      int n = nb0 + nn;
      float z = (s_dist[a][n]*0.1f - mu) * INV_SIG;
      float z2 = z*z;
      if (z2 < 60.f) acc = fmaf(su.a.logit[a][n], __expf(-z2), acc);
    }
    acc += __shfl_xor_sync(0xffffffffu, acc, 1);
    if (hh == 0) g_cb[(size_t)(a0+a)*320 + 256 + j] = acc;
  }
  group_barrier(gid);

  // ========== S4: n_tilde = attn @ nf  (4 tiles x splitK8 = 32) ================
  {
    const int nx = inst & 3, z = inst >> 2;
    gemm_tile<0,0,0,true>(g_attn,512,0, nullptr,
        nf + (size_t)gid*131072, 256,
        g_nt + (size_t)z*131072, 256, mrow, nx*64, z*64, z*64+64, gs, half);
  }
  group_barrier(gid);

  // ========== S5: upd = [sum8 nt | s] @ Wkv_v.T  (4 tiles x splitK5 = 20) ======
  if (inst < 20){
    const int nx = inst & 3, z = inst >> 2;
    gemm_tile<0,0,1,false>(nullptr,0,0, nullptr,
        Wkv + (size_t)256*320, 320,
        g_upd + (size_t)z*131072, 256, mrow, nx*64, z*64, z*64+64, gs, half);
  }
  group_barrier(gid);

  // ========== S6: af = LN1(afeat + sum5(upd) + bkv_v) ==========================
  lnP<5>(afeat, g_upd, 131072, bkv + 256, ln1g, ln1b, g_af);
  group_barrier(gid);

  // ========== S7: m1 = af @ W1.T  (8 tiles x splitK4 = 32) =====================
  {
    const int nx = inst & 7, z = inst >> 3;
    gemm_tile<0,0,0,false>(g_af,256,0, nullptr, W1,256,
        g_m1 + (size_t)z*262144, 512, mrow, nx*64, z*64, z*64+64, gs, half);
  }
  group_barrier(gid);

  // ========== S8: m2; A = relu(sum4 m1 + b1)  (8 tiles x splitK4 = 32) =========
  {
    const int nx = inst & 7, z = inst >> 3;
    gemm_tile<4,1,0,false>(g_m1,512,262144, b1, W2,512,
        g_m2 + (size_t)z*262144, 512, mrow, nx*64, z*128, z*128+128, gs, half);
  }
  group_barrier(gid);

  // ========== S9: m3; A = relu(sum4 m2 + b2)  (4 tiles x splitK8 = 32) =========
  {
    const int nx = inst & 3, z = inst >> 2;
    gemm_tile<4,1,0,false>(g_m2,512,262144, b2, W3,512,
        g_m3 + (size_t)z*131072, 256, mrow, nx*64, z*64, z*64+64, gs, half);
  }
  group_barrier(gid);

  // ========== S10: out = LN2(af + sum8(m3) + b3) ===============================
  lnP<8>(g_af, g_m3, 131072, b3, ln2g, ln2b, out);
}

// ------------------------- launch ----------------------------------------------
extern "C" void kernel_launch(void* const* d_in, const int* in_sizes, int n_in,
                              void* d_out, int out_size)
{
  const float* anchor_x        = (const float*)d_in[0];
  const float* node_x          = (const float*)d_in[1];
  const float* anchor_features = (const float*)d_in[2];
  const float* node_features   = (const float*)d_in[3];
  const float* node_mask       = (const float*)d_in[6];
  const float* Wq              = (const float*)d_in[7];
  const float* bq              = (const float*)d_in[8];
  const float* Wkv             = (const float*)d_in[9];
  const float* bkv             = (const float*)d_in[10];
  const float* ln1_g           = (const float*)d_in[11];
  const float* ln1_b           = (const float*)d_in[12];
  const float* W1              = (const float*)d_in[13];
  const float* b1              = (const float*)d_in[14];
  const float* W2              = (const float*)d_in[15];
  const float* b2              = (const float*)d_in[16];
  const float* W3              = (const float*)d_in[17];
  const float* b3              = (const float*)d_in[18];
  const float* ln2_g           = (const float*)d_in[19];
  const float* ln2_b           = (const float*)d_in[20];
  float* out = (float*)d_out;

  mega<<<NBLK, NTHR>>>(anchor_x, node_x, anchor_features, node_features,
                       node_mask, Wq, bq, Wkv, bkv, ln1_g, ln1_b,
                       W1, b1, W2, b2, W3, b3, ln2_g, ln2_b, out);
}

// round 14
// speedup vs baseline: 1.2690x; 1.0687x over previous
#include <cuda_runtime.h>
#include <math.h>

#define NBLK 128
#define NTHR 512
#define GSZ  16                 // blocks per group (one batch)
#define H    256
#define HE   64
#define APER 64
#define NPER 512
#define EPSF 1e-8f
#define INFM 1000000.0f
#define MU_STEP (20.0f/63.0f)
#define INV_SIG (64.0f/20.0f)

typedef unsigned long long u64;

// ------------------------- scratch (device globals) --------------------------
__device__ float g_q  [4*512*256];   // q partials (splitK4)
__device__ float g_qke[4*512*320];   // qke partials (splitK4)
__device__ float g_attn[512*512];    // softmax probs
__device__ float g_nt [8*512*256];   // n_tilde partials (splitK8)
__device__ float g_cb [512*320];     // s in cols [256,320)
__device__ float g_upd[5*512*256];   // upd partials (splitK5)
__device__ float g_af [512*256];
__device__ float g_m1 [4*512*512];
__device__ float g_m2 [4*512*512];
__device__ float g_m3 [8*512*256];

__device__ unsigned g_gcnt[8*32];    // per-group barrier (padded lines)
__device__ unsigned g_gep [8*32];

// ------------------------- f32x2 helpers ---------------------------------------
__device__ __forceinline__ void ffma2(u64 &d, u64 a, u64 b){
  asm("fma.rn.f32x2 %0, %1, %2, %0;" : "+l"(d) : "l"(a), "l"(b));
}
__device__ __forceinline__ u64 pack2(float x, float y){
  u64 r; asm("mov.b64 %0, {%1, %2};" : "=l"(r) : "f"(x), "f"(y)); return r;
}
__device__ __forceinline__ float2 unpack2(u64 v){
  float2 r; asm("mov.b64 {%0, %1}, %2;" : "=f"(r.x), "=f"(r.y) : "l"(v)); return r;
}

// ------------------------- reductions -----------------------------------------
__device__ __forceinline__ float warp_reduce_sum(float v){
#pragma unroll
  for (int o=16;o>0;o>>=1) v += __shfl_xor_sync(0xffffffffu, v, o);
  return v;
}
__device__ __forceinline__ float warp_reduce_max(float v){
#pragma unroll
  for (int o=16;o>0;o>>=1) v = fmaxf(v, __shfl_xor_sync(0xffffffffu, v, o));
  return v;
}

// Group barrier: 16 co-resident blocks of one group.
__device__ __forceinline__ void group_barrier(int gid){
  __syncthreads();
  if (threadIdx.x == 0){
    unsigned* cnt = &g_gcnt[gid*32];
    unsigned* ep  = &g_gep [gid*32];
    __threadfence();
    unsigned e = atomicAdd(ep, 0u);
    unsigned prev = atomicAdd(cnt, 1u);
    if (prev == GSZ - 1){
      atomicExch(cnt, 0u);
      __threadfence();
      atomicAdd(ep, 1u);
    } else {
      volatile unsigned* p = ep;
      while (*p == e) { }
      __threadfence();
    }
  }
  __syncthreads();
}

// Named barrier: syncs one 256-thread half independently.
__device__ __forceinline__ void half_sync(int half){
  asm volatile("bar.sync %0, 256;" :: "r"(1 + half) : "memory");
}

// ------------------------- shared memory ---------------------------------------
struct GemmSmem { float As[2][16][68]; float Bs[2][16][68]; };
struct AttnA    { float qk[4][H]; float qek[4][HE]; float logit[4][NPER]; };
union  __align__(16) SU { GemmSmem g[2]; AttnA a; };

// ------------------------- GEMM tile 64x64, 256 thr/instance, FFMA2 ------------
// A row-major. APART>0: A := (sum_{p<APART} A[p*astride]) + abias[k]; relu iff ARELU.
// UPD: A-load = sum8 g_nt (k<256) | g_cb s-cols (k>=256).
// B_KN: B is (K,N) row-major; else (N,K) row-major (@W.T form).
template<int APART, int ARELU, int UPD, bool B_KN>
__device__ void gemm_tile(const float* __restrict__ A, int lda, size_t astride,
                          const float* __restrict__ abias,
                          const float* __restrict__ B, int ldb,
                          float* __restrict__ C, int ldc,
                          int m0, int n0, int kbeg, int kend,
                          GemmSmem* sm, int half)
{
  const int t  = threadIdx.x & 255;
  const int tx = t & 15, ty = t >> 4;

  const int a_i0 = t >> 2, a_i1 = t & 3;         // m-row(64), k-grp(4)
  int b_i0, b_i1;
  if (B_KN){ b_i0 = t >> 4; b_i1 = t & 15; }     // k-row(16), n-grp(16)
  else     { b_i0 = t >> 2; b_i1 = t & 3;  }     // n-row(64), k-grp(4)

  auto loadA = [&](int k0)->float4 {
    if (UPD){
      const int col = k0 + a_i1*4;
      const int row = m0 + a_i0;
      if (col < 256){
        const size_t o = (size_t)row*256 + col;
        float4 v = *(const float4*)(g_nt + o);
#pragma unroll
        for (int p = 1; p < 8; p++){
          float4 w = *(const float4*)(g_nt + (size_t)p*131072 + o);
          v.x+=w.x; v.y+=w.y; v.z+=w.z; v.w+=w.w;
        }
        return v;
      }
      return *(const float4*)(g_cb + (size_t)row*320 + col);
    }
    const size_t o = (size_t)(m0 + a_i0)*lda + k0 + a_i1*4;
    float4 v = *(const float4*)(A + o);
    if (APART > 0){
#pragma unroll
      for (int p = 1; p < APART; p++){
        float4 w = *(const float4*)(A + p*astride + o);
        v.x+=w.x; v.y+=w.y; v.z+=w.z; v.w+=w.w;
      }
      float4 vb = *(const float4*)(abias + k0 + a_i1*4);
      v.x += vb.x; v.y += vb.y; v.z += vb.z; v.w += vb.w;
      if (ARELU){
        v.x = fmaxf(v.x,0.f); v.y = fmaxf(v.y,0.f);
        v.z = fmaxf(v.z,0.f); v.w = fmaxf(v.w,0.f);
      }
    }
    return v;
  };
  auto loadB = [&](int k0)->float4 {
    if (B_KN) return *(const float4*)(B + (size_t)(k0 + b_i0)*ldb + n0 + b_i1*4);
    return *(const float4*)(B + (size_t)(n0 + b_i0)*ldb + k0 + b_i1*4);
  };
  auto storeA = [&](int buf, float4 v){
    sm->As[buf][a_i1*4+0][a_i0] = v.x;
    sm->As[buf][a_i1*4+1][a_i0] = v.y;
    sm->As[buf][a_i1*4+2][a_i0] = v.z;
    sm->As[buf][a_i1*4+3][a_i0] = v.w;
  };
  auto storeB = [&](int buf, float4 v){
    if (B_KN) *(float4*)&sm->Bs[buf][b_i0][b_i1*4] = v;
    else {
      sm->Bs[buf][b_i1*4+0][b_i0] = v.x;
      sm->Bs[buf][b_i1*4+1][b_i0] = v.y;
      sm->Bs[buf][b_i1*4+2][b_i0] = v.z;
      sm->Bs[buf][b_i1*4+3][b_i0] = v.w;
    }
  };

  u64 acc[2][4];
#pragma unroll
  for (int i=0;i<2;i++)
#pragma unroll
    for (int j=0;j<4;j++) acc[i][j] = 0ULL;

  half_sync(half);
  storeA(0, loadA(kbeg));
  storeB(0, loadB(kbeg));
  half_sync(half);

  int buf = 0;
  for (int k0 = kbeg + 16; ; k0 += 16, buf ^= 1){
    const bool more = (k0 < kend);
    float4 pa, pb;
    if (more){ pa = loadA(k0); pb = loadB(k0); }
#pragma unroll
    for (int kk = 0; kk < 16; kk++){
      ulonglong2 aa = *(const ulonglong2*)&sm->As[buf][kk][ty*4];
      float4 bv = *(const float4*)&sm->Bs[buf][kk][tx*4];
      u64 b0 = pack2(bv.x, bv.x), b1 = pack2(bv.y, bv.y);
      u64 b2 = pack2(bv.z, bv.z), b3 = pack2(bv.w, bv.w);
      ffma2(acc[0][0], aa.x, b0); ffma2(acc[0][1], aa.x, b1);
      ffma2(acc[0][2], aa.x, b2); ffma2(acc[0][3], aa.x, b3);
      ffma2(acc[1][0], aa.y, b0); ffma2(acc[1][1], aa.y, b1);
      ffma2(acc[1][2], aa.y, b2); ffma2(acc[1][3], aa.y, b3);
    }
    if (!more) break;
    storeA(buf^1, pa);
    storeB(buf^1, pb);
    half_sync(half);
  }

  float2 r0[4], r1[4];
#pragma unroll
  for (int j=0;j<4;j++){ r0[j] = unpack2(acc[0][j]); r1[j] = unpack2(acc[1][j]); }
  const int m = m0 + ty*4;
  *(float4*)(C + (size_t)(m+0)*ldc + n0 + tx*4) = make_float4(r0[0].x, r0[1].x, r0[2].x, r0[3].x);
  *(float4*)(C + (size_t)(m+1)*ldc + n0 + tx*4) = make_float4(r0[0].y, r0[1].y, r0[2].y, r0[3].y);
  *(float4*)(C + (size_t)(m+2)*ldc + n0 + tx*4) = make_float4(r1[0].x, r1[1].x, r1[2].x, r1[3].x);
  *(float4*)(C + (size_t)(m+3)*ldc + n0 + tx*4) = make_float4(r1[0].y, r1[1].y, r1[2].y, r1[3].y);
}

// ------------------------- residual + LN (4 rows/block, P partials) ------------
template<int P>
__device__ void lnP(const float* __restrict__ r,
                    const float* __restrict__ part, size_t pstride,
                    const float* __restrict__ bias,
                    const float* __restrict__ g, const float* __restrict__ b,
                    float* __restrict__ o)
{
  const int w = threadIdx.x >> 5, lane = threadIdx.x & 31;
  if (w >= 4) return;
  const size_t row = (size_t)blockIdx.x*4 + w;
  float v[8]; float s = 0.f;
#pragma unroll
  for (int i=0;i<8;i++){
    int c = lane + i*32;
    size_t idx = row*H + c;
    float x = r[idx] + bias[c];
#pragma unroll
    for (int p=0;p<P;p++) x += part[(size_t)p*pstride + idx];
    v[i] = x; s += x;
  }
  s = warp_reduce_sum(s);
  float mean = s * (1.f/H);
  float s2 = 0.f;
#pragma unroll
  for (int i=0;i<8;i++){ float d = v[i]-mean; s2 += d*d; }
  s2 = warp_reduce_sum(s2);
  float inv = rsqrtf(s2*(1.f/H) + 1e-5f);
#pragma unroll
  for (int i=0;i<8;i++){
    int c = lane + i*32;
    o[row*H+c] = (v[i]-mean)*inv*g[c] + b[c];
  }
}

// ------------------------- megakernel ------------------------------------------
__global__ __launch_bounds__(NTHR)
void mega(const float* __restrict__ anchor_x,
          const float* __restrict__ node_x,
          const float* __restrict__ afeat,
          const float* __restrict__ nf,
          const float* __restrict__ nmask,
          const float* __restrict__ Wq,  const float* __restrict__ bq,
          const float* __restrict__ Wkv, const float* __restrict__ bkv,
          const float* __restrict__ ln1g, const float* __restrict__ ln1b,
          const float* __restrict__ W1, const float* __restrict__ b1,
          const float* __restrict__ W2, const float* __restrict__ b2,
          const float* __restrict__ W3, const float* __restrict__ b3,
          const float* __restrict__ ln2g, const float* __restrict__ ln2b,
          float* __restrict__ out)
{
  __shared__ SU su;
  __shared__ __align__(16) float s_dist[4][NPER];
  __shared__ float s_ax[4][3];
  __shared__ float s_qbk[4];
  __shared__ float s_bqbk;
  __shared__ int   s_list[NPER];
  __shared__ int   s_cnt;
  __shared__ float s_red[32];

  const int tid = threadIdx.x, bid = blockIdx.x;
  const int lane = tid & 31, warp = tid >> 5;
  const int half = tid >> 8;
  GemmSmem* gs = &su.g[half];
  const int gid  = bid >> 4;                      // group 0..7 (one batch)
  const int inst = half*GSZ + (bid & 15);         // 0..31 per group
  const int mrow = gid * 64;                      // group's anchor-row base
  const int a0   = bid * 4;                       // block's own anchors
  const int nbase = gid * NPER;

  // ========== S1: attn prep + bq.bk + q partials (4 tiles x splitK4 = 16) ======
  if (tid == 0) s_cnt = 0;
  if (tid < 12) s_ax[tid/3][tid%3] = anchor_x[(size_t)(a0 + tid/3)*3 + (tid%3)];
  __syncthreads();
  {
    const int n = tid & 511, ng = nbase + n;
    if (tid < NPER){
      const float x0 = node_x[(size_t)3*ng+0];
      const float x1 = node_x[(size_t)3*ng+1];
      const float x2 = node_x[(size_t)3*ng+2];
#pragma unroll
      for (int a=0;a<4;a++){
        float dx = s_ax[a][0]-x0+EPSF;
        float dy = s_ax[a][1]-x1+EPSF;
        float dz = s_ax[a][2]-x2+EPSF;
        s_dist[a][n] = sqrtf(dx*dx + dy*dy + dz*dz);
      }
      if (nmask[ng] == 0.0f){
        int p = atomicAdd(&s_cnt, 1);
        s_list[p] = n;
      }
    }
  }
  if (warp == 8){                                 // bq . bk
    float s = 0.f;
#pragma unroll
    for (int kk=0;kk<8;kk++) s = fmaf(bq[lane+kk*32], bkv[lane+kk*32], s);
    s = warp_reduce_sum(s);
    if (lane == 0) s_bqbk = s;
  }
  if (inst < 16){                                 // q = afeat @ Wq.T (partials)
    const int nx = inst & 3, z = inst >> 2;
    gemm_tile<0,0,0,false>(afeat,256,0, nullptr, Wq,256,
        g_q + (size_t)z*131072, 256, mrow, nx*64, z*64, z*64+64, gs, half);
  }
  group_barrier(gid);

  // ========== S2: qke = (sum q + bq) @ Wkv[0:256,:]  (5 tiles x splitK4 = 20) ==
  if (inst < 20){
    const int nx = inst % 5, z = inst / 5;
    gemm_tile<4,0,0,true>(g_q,256,131072, bq, Wkv,320,
        g_qke + (size_t)z*163840, 320, mrow, nx*64, z*64, z*64+64, gs, half);
  }
  group_barrier(gid);

  // ========== S3: attention (block-local) ======================================
  // qbk[a] = q[a].bkv + bq.bk
  if (warp < 4){
    const size_t row = (size_t)(a0 + warp)*256;
    float s = 0.f;
#pragma unroll
    for (int kk=0;kk<8;kk++){
      int c = lane + kk*32;
      float qv = g_q[row+c] + g_q[131072+row+c] + g_q[2*131072+row+c]
               + g_q[3*131072+row+c] + bq[c];
      s = fmaf(qv, bkv[c], s);
    }
    s = warp_reduce_sum(s);
    if (lane == 0) s_qbk[warp] = s + s_bqbk;
  }
  for (int i = tid; i < 4*NPER; i += NTHR)
    su.a.logit[i>>9][i & 511] = 0.f;
  // load qk/qek: vectorized 4-partial sum (4*320 floats = 320 float4)
  for (int i = tid; i < 320; i += NTHR){
    int r = i / 80, c4 = (i - r*80) * 4;
    size_t idx = (size_t)(a0 + r)*320 + c4;
    float4 v0 = *(const float4*)(g_qke + idx);
    float4 v1 = *(const float4*)(g_qke + 163840 + idx);
    float4 v2 = *(const float4*)(g_qke + 2*163840 + idx);
    float4 v3 = *(const float4*)(g_qke + 3*163840 + idx);
    float4 v = make_float4(v0.x+v1.x+v2.x+v3.x, v0.y+v1.y+v2.y+v3.y,
                           v0.z+v1.z+v2.z+v3.z, v0.w+v1.w+v2.w+v3.w);
    if (c4 < 256) *(float4*)&su.a.qk[r][c4] = v;
    else          *(float4*)&su.a.qek[r][c4-256] = v;
  }
  __syncthreads();

  {                                               // masked logits only
    const int cnt = s_cnt;
    const float mu0 = (float)lane * MU_STEP;
    const float mu1 = (float)(lane+32) * MU_STEP;
    for (int i = warp; i < cnt; i += 16){
      const int n = s_list[i], ng = nbase + n;
      const float4* nf4 = (const float4*)(nf + (size_t)ng*H);
      float4 u0 = nf4[lane], u1 = nf4[lane+32];
#pragma unroll
      for (int a=0;a<4;a++){
        float t2 = s_dist[a][n] * 0.1f;
        float z0 = (t2 - mu0)*INV_SIG, z1 = (t2 - mu1)*INV_SIG;
        float z0s = z0*z0, z1s = z1*z1;
        float acc = 0.f;
        if (z0s < 64.f) acc  = __expf(-z0s) * su.a.qek[a][lane];
        if (z1s < 64.f) acc += __expf(-z1s) * su.a.qek[a][lane+32];
        const float4* qa = (const float4*)su.a.qk[a];
        float4 q0 = qa[lane], q1 = qa[lane+32];
        acc = fmaf(u0.x,q0.x, fmaf(u0.y,q0.y, fmaf(u0.z,q0.z, fmaf(u0.w,q0.w, acc))));
        acc = fmaf(u1.x,q1.x, fmaf(u1.y,q1.y, fmaf(u1.z,q1.z, fmaf(u1.w,q1.w, acc))));
        acc = warp_reduce_sum(acc);
        if (lane == 0) su.a.logit[a][n] = (acc + s_qbk[a]) * (-INFM);
      }
    }
  }
  __syncthreads();

  // ---- softmax: all 4 anchors in parallel (warp = anchor x quarter) ----------
  {
    const int a = warp & 3, qr = warp >> 2;
    const int nb = qr*128 + lane;
    float l0 = su.a.logit[a][nb+0],  l1 = su.a.logit[a][nb+32];
    float l2 = su.a.logit[a][nb+64], l3 = su.a.logit[a][nb+96];
    float m = fmaxf(fmaxf(l0,l1), fmaxf(l2,l3));
    m = warp_reduce_max(m);
    if (lane == 0) s_red[warp] = m;
    __syncthreads();
    float mx = fmaxf(fmaxf(s_red[a], s_red[a+4]), fmaxf(s_red[a+8], s_red[a+12]));
    float e0 = __expf(l0-mx), e1 = __expf(l1-mx);
    float e2 = __expf(l2-mx), e3 = __expf(l3-mx);
    float s = warp_reduce_sum(e0+e1+e2+e3);
    if (lane == 0) s_red[16+warp] = s;
    __syncthreads();
    float inv = 1.f / (s_red[16+a] + s_red[20+a] + s_red[24+a] + s_red[28+a]);
    float p0 = e0*inv, p1 = e1*inv, p2 = e2*inv, p3 = e3*inv;
    su.a.logit[a][nb+0]  = p0; su.a.logit[a][nb+32] = p1;
    su.a.logit[a][nb+64] = p2; su.a.logit[a][nb+96] = p3;
    const size_t gb = (size_t)(a0+a)*NPER + nb;
    g_attn[gb+0]  = p0; g_attn[gb+32] = p1;
    g_attn[gb+64] = p2; g_attn[gb+96] = p3;
  }
  __syncthreads();

  {                                               // C1: s[a][j] = sum attn*rbf
    const int a = tid >> 7, r = tid & 127, j = r >> 1, hh = r & 1;
    const float mu = (float)j * MU_STEP;
    float acc = 0.f;
    const int nb0 = hh * 256;
#pragma unroll 4
    for (int nn=0; nn<256; nn++){
      int n = nb0 + nn;
      float z = (s_dist[a][n]*0.1f - mu) * INV_SIG;
      float z2 = z*z;
      if (z2 < 16.f) acc = fmaf(su.a.logit[a][n], __expf(-z2), acc);
    }
    acc += __shfl_xor_sync(0xffffffffu, acc, 1);
    if (hh == 0) g_cb[(size_t)(a0+a)*320 + 256 + j] = acc;
  }
  group_barrier(gid);

  // ========== S4: n_tilde = attn @ nf  (4 tiles x splitK8 = 32) ================
  {
    const int nx = inst & 3, z = inst >> 2;
    gemm_tile<0,0,0,true>(g_attn,512,0, nullptr,
        nf + (size_t)gid*131072, 256,
        g_nt + (size_t)z*131072, 256, mrow, nx*64, z*64, z*64+64, gs, half);
  }
  group_barrier(gid);

  // ========== S5: upd = [sum8 nt | s] @ Wkv_v.T  (4 tiles x splitK5 = 20) ======
  if (inst < 20){
    const int nx = inst & 3, z = inst >> 2;
    gemm_tile<0,0,1,false>(nullptr,0,0, nullptr,
        Wkv + (size_t)256*320, 320,
        g_upd + (size_t)z*131072, 256, mrow, nx*64, z*64, z*64+64, gs, half);
  }
  group_barrier(gid);

  // ========== S6: af = LN1(afeat + sum5(upd) + bkv_v) ==========================
  lnP<5>(afeat, g_upd, 131072, bkv + 256, ln1g, ln1b, g_af);
  group_barrier(gid);

  // ========== S7: m1 = af @ W1.T  (8 tiles x splitK4 = 32) =====================
  {
    const int nx = inst & 7, z = inst >> 3;
    gemm_tile<0,0,0,false>(g_af,256,0, nullptr, W1,256,
        g_m1 + (size_t)z*262144, 512, mrow, nx*64, z*64, z*64+64, gs, half);
  }
  group_barrier(gid);

  // ========== S8: m2; A = relu(sum4 m1 + b1)  (8 tiles x splitK4 = 32) =========
  {
    const int nx = inst & 7, z = inst >> 3;
    gemm_tile<4,1,0,false>(g_m1,512,262144, b1, W2,512,
        g_m2 + (size_t)z*262144, 512, mrow, nx*64, z*128, z*128+128, gs, half);
  }
  group_barrier(gid);

  // ========== S9: m3; A = relu(sum4 m2 + b2)  (4 tiles x splitK8 = 32) =========
  {
    const int nx = inst & 3, z = inst >> 2;
    gemm_tile<4,1,0,false>(g_m2,512,262144, b2, W3,512,
        g_m3 + (size_t)z*131072, 256, mrow, nx*64, z*64, z*64+64, gs, half);
  }
  group_barrier(gid);

  // ========== S10: out = LN2(af + sum8(m3) + b3) ===============================
  lnP<8>(g_af, g_m3, 131072, b3, ln2g, ln2b, out);
}

// ------------------------- launch ----------------------------------------------
extern "C" void kernel_launch(void* const* d_in, const int* in_sizes, int n_in,
                              void* d_out, int out_size)
{
  const float* anchor_x        = (const float*)d_in[0];
  const float* node_x          = (const float*)d_in[1];
  const float* anchor_features = (const float*)d_in[2];
  const float* node_features   = (const float*)d_in[3];
  const float* node_mask       = (const float*)d_in[6];
  const float* Wq              = (const float*)d_in[7];
  const float* bq              = (const float*)d_in[8];
  const float* Wkv             = (const float*)d_in[9];
  const float* bkv             = (const float*)d_in[10];
  const float* ln1_g           = (const float*)d_in[11];
  const float* ln1_b           = (const float*)d_in[12];
  const float* W1              = (const float*)d_in[13];
  const float* b1              = (const float*)d_in[14];
  const float* W2              = (const float*)d_in[15];
  const float* b2              = (const float*)d_in[16];
  const float* W3              = (const float*)d_in[17];
  const float* b3              = (const float*)d_in[18];
  const float* ln2_g           = (const float*)d_in[19];
  const float* ln2_b           = (const float*)d_in[20];
  float* out = (float*)d_out;

  mega<<<NBLK, NTHR>>>(anchor_x, node_x, anchor_features, node_features,
                       node_mask, Wq, bq, Wkv, bkv, ln1_g, ln1_b,
                       W1, b1, W2, b2, W3, b3, ln2_g, ln2_b, out);
}